// round 16
// baseline (speedup 1.0000x reference)
#include <cuda_runtime.h>
#include <math.h>

#define WPB   8
#define NC    1000
#define NF4   250
#define NK    10
#define L2E   1.4426950408889634f
#define STAGES 3
#define CHUNK_ROWS  8
#define CHUNK_BYTES (CHUNK_ROWS * NC * 4)          // 32000
#define NBLK  296                                  // 148 SMs x 2 blocks
#define BUF_OFF 128
#define SMEM_DYN (BUF_OFF + STAGES * CHUNK_BYTES)  // 96128

__device__ __forceinline__ float ex2f(float x) {
    float r; asm("ex2.approx.f32 %0, %1;" : "=f"(r) : "f"(x)); return r;
}
__device__ __forceinline__ float lg2f(float x) {
    float r; asm("lg2.approx.f32 %0, %1;" : "=f"(r) : "f"(x)); return r;
}
__device__ __forceinline__ float pow9f(float x) {
    float x2 = x * x, x4 = x2 * x2, x8 = x4 * x4; return x8 * x;
}
__device__ __forceinline__ float pow10f(float x) {
    float x2 = x * x, x4 = x2 * x2, x8 = x4 * x4; return x8 * x2;
}
__device__ __forceinline__ float rootf(float y, float inv_p) {
    return ex2f(lg2f(y) * inv_p);
}
__device__ __forceinline__ unsigned s2u(const void* p) {
    unsigned a;
    asm("{ .reg .u64 t; cvta.to.shared.u64 t, %1; cvt.u32.u64 %0, t; }" : "=r"(a) : "l"(p));
    return a;
}

#define MBAR_INIT(a, c) \
    asm volatile("mbarrier.init.shared.b64 [%0], %1;" :: "r"(a), "r"(c) : "memory")
#define MBAR_EXPECT_TX(a, b) \
    asm volatile("mbarrier.arrive.expect_tx.shared.b64 _, [%0], %1;" :: "r"(a), "r"(b) : "memory")
#define MBAR_ARRIVE(a) \
    asm volatile("mbarrier.arrive.shared.b64 _, [%0];" :: "r"(a) : "memory")
#define MBAR_WAIT(a, par) do {                                                   \
    unsigned _m = (a), _p = (par), _d;                                           \
    asm volatile("{\n\t.reg .pred p;\n\t"                                        \
        "mbarrier.try_wait.parity.acquire.cta.shared::cta.b64 p, [%1], %2;\n\t"  \
        "selp.b32 %0, 1, 0, p;\n\t}"                                             \
        : "=r"(_d) : "r"(_m), "r"(_p) : "memory");                               \
    if (!_d) {                                                                   \
        asm volatile("{\n\t.reg .pred P1;\n\t"                                   \
            "WL_%=:\n\t"                                                         \
            "mbarrier.try_wait.parity.acquire.cta.shared::cta.b64 P1, [%0], %1, 0x989680;\n\t" \
            "@P1 bra.uni WD_%=;\n\t"                                             \
            "bra.uni WL_%=;\n\t"                                                 \
            "WD_%=:\n\t}"                                                        \
            :: "r"(_m), "r"(_p) : "memory");                                     \
    }                                                                            \
} while (0)
#define BULK_G2S(dst, src, bytes, mbar) \
    asm volatile("cp.async.bulk.shared::cta.global.mbarrier::complete_tx::bytes " \
                 "[%0], [%1], %2, [%3];" \
                 :: "r"(dst), "l"(src), "r"(bytes), "r"(mbar) : "memory")

__global__ __launch_bounds__(WPB * 32)
void boilerplate_loss_kernel(const float* __restrict__ y_pred,
                             const int*   __restrict__ y_attack,
                             float*       __restrict__ out,
                             int nrows)
{
    extern __shared__ char dsm[];
    __shared__ unsigned int smask[WPB][32];

    const unsigned sb  = s2u(dsm);            // full[s]=sb+8s, empty[s]=sb+32+8s
    const int tid  = threadIdx.x;
    const int warp = tid >> 5;
    const int lane = tid & 31;
    const int nchunks = nrows / CHUNK_ROWS;

    if (tid == 0) {
        #pragma unroll
        for (int s = 0; s < STAGES; s++) {
            MBAR_INIT(sb + 8 * s, 1);          // full: single expect_tx arrive
            MBAR_INIT(sb + 32 + 8 * s, WPB);   // empty: one arrive per warp
        }
        // prologue: fill the ring
        int i = 0;
        for (int c = blockIdx.x; c < nchunks && i < STAGES; c += gridDim.x, i++) {
            MBAR_EXPECT_TX(sb + 8 * i, CHUNK_BYTES);
            BULK_G2S(sb + BUF_OFF + i * CHUNK_BYTES,
                     (const char*)y_pred + (size_t)c * CHUNK_BYTES,
                     CHUNK_BYTES, sb + 8 * i);
        }
    }
    __syncthreads();

    int k = 0;
    for (int c = blockIdx.x; c < nchunks; c += gridDim.x, k++) {
        const int st = k % STAGES;
        const int u  = k / STAGES;

        MBAR_WAIT(sb + 8 * st, u & 1);         // wait chunk data

        const float*  rowb  = (const float*)(dsm + BUF_OFF + st * CHUNK_BYTES) + warp * NC;
        const float4* rowp4 = (const float4*)rowb;
        const int row = c * CHUNK_ROWS + warp;

        // --- gather attack indices + logits (from smem row) ---
        int   idx = (lane < NK) ? y_attack[row * NK + lane] : 0;
        float xa  = (lane < NK) ? rowb[idx] : 0.0f;

        // --- sum(exp) + unconditional max over the row (smem, LDS.128) ---
        float s0 = 0.f, s1 = 0.f;
        float mxa = -INFINITY;
        #pragma unroll
        for (int j = 0; j < 8; j++) {
            int i = lane + 32 * j;
            float4 q = (j < 7 || i < NF4) ? rowp4[i]
                     : make_float4(-INFINITY, -INFINITY, -INFINITY, -INFINITY);
            s0 += ex2f(q.x * L2E) + ex2f(q.y * L2E);
            s1 += ex2f(q.z * L2E) + ex2f(q.w * L2E);
            mxa = fmaxf(mxa, fmaxf(fmaxf(q.x, q.y), fmaxf(q.z, q.w)));
        }
        float s = s0 + s1;

        // --- fused butterfly: (sum, max_all, max_attack, min_attack) ---
        float mxatt = (lane < NK) ? xa : -INFINITY;
        float mnatt = (lane < NK) ? xa :  INFINITY;
        #pragma unroll
        for (int o = 16; o > 0; o >>= 1) {
            s     +=        __shfl_xor_sync(0xffffffffu, s,     o);
            mxa    = fmaxf(mxa,   __shfl_xor_sync(0xffffffffu, mxa,   o));
            mxatt  = fmaxf(mxatt, __shfl_xor_sync(0xffffffffu, mxatt, o));
            mnatt  = fminf(mnatt, __shfl_xor_sync(0xffffffffu, mnatt, o));
        }

        // --- non-attack max; rare warp-uniform path rescans smem row ---
        float mx_non;
        if (mxa == mxatt) {
            smask[warp][lane] = 0u;
            __syncwarp();
            if (lane < NK) atomicOr(&smask[warp][idx >> 5], 1u << (idx & 31));
            __syncwarp();
            float m = -INFINITY;
            #pragma unroll 2
            for (int j = 0; j < 8; j++) {
                int i = lane + 32 * j;
                if (i < NF4) {
                    float4 q = rowp4[i];
                    unsigned int bits = (smask[warp][i >> 3] >> ((i & 7) * 4)) & 0xFu;
                    if (!(bits & 1u)) m = fmaxf(m, q.x);
                    if (!(bits & 2u)) m = fmaxf(m, q.y);
                    if (!(bits & 4u)) m = fmaxf(m, q.z);
                    if (!(bits & 8u)) m = fmaxf(m, q.w);
                }
            }
            #pragma unroll
            for (int o = 16; o > 0; o >>= 1)
                m = fmaxf(m, __shfl_xor_sync(0xffffffffu, m, o));
            mx_non = m;
            __syncwarp();
        } else {
            mx_non = mxa;
        }

        // --- probs + macro (pmin via monotonicity of exp / positive 1/s) ---
        float inv_s = __frcp_rn(s);
        float pmin     = ex2f(mnatt  * L2E) * inv_s;
        float pmax_non = ex2f(mx_non * L2E) * inv_s;
        float macro = pmax_non - pmin;

        // --- sorting term ---
        float p = (lane < NK) ? (ex2f(xa * L2E) * inv_s) : 0.0f;
        float pnext = __shfl_down_sync(0xffffffffu, p, 1);
        float term = 0.0f;
        if (lane < NK - 1) {
            float d  = pnext - p;
            float sv = 5.0f + 5.0f * d;
            term = pow9f(sv);
        }
        #pragma unroll
        for (int o = 16; o > 0; o >>= 1)
            term += __shfl_xor_sync(0xffffffffu, term, o);

        if (lane == 0) {
            float gm9 = rootf(term * (1.0f / 9.0f), 1.0f / 9.0f);
            float sorting = (gm9 - 5.0f) * 0.2f;
            float c0 = 5.0f + 5.0f * macro;
            float c1 = 5.0f + 5.0f * sorting;
            float m = (pow10f(c0) + pow10f(c1)) * 0.5f;
            float fin = rootf(m, 0.1f);
            out[row] = (fin - 5.0f) * 0.2f;
        }

        // --- release buffer; producer refills it with chunk k+STAGES ---
        __syncwarp();
        if (lane == 0) MBAR_ARRIVE(sb + 32 + 8 * st);

        if (tid == 0) {
            int cn = c + STAGES * gridDim.x;
            if (cn < nchunks) {
                MBAR_WAIT(sb + 32 + 8 * st, u & 1);   // all 8 warps done with use u
                MBAR_EXPECT_TX(sb + 8 * st, CHUNK_BYTES);
                BULK_G2S(sb + BUF_OFF + st * CHUNK_BYTES,
                         (const char*)y_pred + (size_t)cn * CHUNK_BYTES,
                         CHUNK_BYTES, sb + 8 * st);
            }
        }
    }
}

extern "C" void kernel_launch(void* const* d_in, const int* in_sizes, int n_in,
                              void* d_out, int out_size)
{
    const float* y_pred   = (const float*)d_in[0];
    const int*   y_attack = (const int*)d_in[1];
    float*       out      = (float*)d_out;
    int nrows = in_sizes[1] / NK;   // 32768 (multiple of CHUNK_ROWS)

    static int smem_set = 0;
    if (!smem_set) {
        cudaFuncSetAttribute(boilerplate_loss_kernel,
                             cudaFuncAttributeMaxDynamicSharedMemorySize, SMEM_DYN);
        smem_set = 1;
    }
    int blocks = NBLK;
    int nchunks = nrows / CHUNK_ROWS;
    if (blocks > nchunks) blocks = nchunks;
    boilerplate_loss_kernel<<<blocks, WPB * 32, SMEM_DYN>>>(y_pred, y_attack, out, nrows);
}

// round 17
// speedup vs baseline: 1.0857x; 1.0857x over previous
#include <cuda_runtime.h>
#include <math.h>

#define WPB  8          // warps per block
#define NC   1000       // classes
#define ROWB 4000       // bytes per row
#define NF8  125        // 32B-chunks per row
#define NF4  250        // float4 per row
#define NK   10         // attack classes per row
#define L2E  1.4426950408889634f
#define NBLK 740        // 148 SMs x 5 blocks/SM, persistent

__device__ __forceinline__ float ex2f(float x) {
    float r; asm("ex2.approx.f32 %0, %1;" : "=f"(r) : "f"(x)); return r;
}
__device__ __forceinline__ float lg2f(float x) {
    float r; asm("lg2.approx.f32 %0, %1;" : "=f"(r) : "f"(x)); return r;
}
__device__ __forceinline__ float pow9f(float x) {
    float x2 = x * x, x4 = x2 * x2, x8 = x4 * x4; return x8 * x;
}
__device__ __forceinline__ float pow10f(float x) {
    float x2 = x * x, x4 = x2 * x2, x8 = x4 * x4; return x8 * x2;
}
__device__ __forceinline__ float rootf(float y, float inv_p) {
    return ex2f(lg2f(y) * inv_p);
}

struct F8 { float a[8]; };

// 256-bit load
__device__ __forceinline__ F8 ldg256(const float* p) {
    F8 v;
    unsigned r0,r1,r2,r3,r4,r5,r6,r7;
    asm("ld.global.nc.v8.b32 {%0,%1,%2,%3,%4,%5,%6,%7}, [%8];"
        : "=r"(r0),"=r"(r1),"=r"(r2),"=r"(r3),
          "=r"(r4),"=r"(r5),"=r"(r6),"=r"(r7) : "l"(p));
    v.a[0]=__int_as_float(r0); v.a[1]=__int_as_float(r1);
    v.a[2]=__int_as_float(r2); v.a[3]=__int_as_float(r3);
    v.a[4]=__int_as_float(r4); v.a[5]=__int_as_float(r5);
    v.a[6]=__int_as_float(r6); v.a[7]=__int_as_float(r7);
    return v;
}

// DMA prefetch a whole row into L2 — no smem, no mbarrier, no line-cap pressure
__device__ __forceinline__ void prefetch_l2(const void* p, int bytes) {
    asm volatile("cp.async.bulk.prefetch.L2.global [%0], %1;" :: "l"(p), "r"(bytes));
}

__global__ __launch_bounds__(WPB * 32, 5)
void boilerplate_loss_kernel(const float* __restrict__ y_pred,
                             const int*   __restrict__ y_attack,
                             float*       __restrict__ out,
                             int nrows)
{
    __shared__ unsigned int smask[WPB][32];   // only touched on the rare path

    const int warp   = threadIdx.x >> 5;
    const int lane   = threadIdx.x & 31;
    const int gwarp  = blockIdx.x * WPB + warp;
    const int nwarps = gridDim.x * WPB;

    // prologue: prefetch this warp's first row
    if (lane == 0 && gwarp < nrows)
        prefetch_l2((const char*)y_pred + (size_t)gwarp * ROWB, ROWB);

    for (int row = gwarp; row < nrows; row += nwarps) {
        const float* rowbase = y_pred + (size_t)row * NC;

        // prefetch NEXT row into L2 while we stream this one
        int nxt = row + nwarps;
        if (lane == 0 && nxt < nrows)
            prefetch_l2((const char*)y_pred + (size_t)nxt * ROWB, ROWB);

        // --- 1) batch the whole row: 4 x LDG.256 per lane ---
        F8 v[4];
        #pragma unroll
        for (int j = 0; j < 4; j++) {
            int i = lane + 32 * j;            // 32-byte chunk index, 0..127
            if (j < 3 || i < NF8) {
                v[j] = ldg256(rowbase + i * 8);
            } else {
                #pragma unroll
                for (int k = 0; k < 8; k++) v[j].a[k] = -INFINITY;
            }
        }

        // --- 2) sum(exp) + unconditional max ---
        float s0 = 0.f, s1 = 0.f;
        float mxa = -INFINITY;
        #pragma unroll
        for (int j = 0; j < 4; j++) {
            s0 += ex2f(v[j].a[0] * L2E) + ex2f(v[j].a[1] * L2E)
                + ex2f(v[j].a[2] * L2E) + ex2f(v[j].a[3] * L2E);
            s1 += ex2f(v[j].a[4] * L2E) + ex2f(v[j].a[5] * L2E)
                + ex2f(v[j].a[6] * L2E) + ex2f(v[j].a[7] * L2E);
            float m01 = fmaxf(fmaxf(v[j].a[0], v[j].a[1]), fmaxf(v[j].a[2], v[j].a[3]));
            float m23 = fmaxf(fmaxf(v[j].a[4], v[j].a[5]), fmaxf(v[j].a[6], v[j].a[7]));
            mxa = fmaxf(mxa, fmaxf(m01, m23));
        }
        float s = s0 + s1;

        // --- 3) gather attack logits (row lines L1-hot) ---
        int   idx = (lane < NK) ? y_attack[row * NK + lane] : 0;
        float xa  = (lane < NK) ? __ldg(&rowbase[idx]) : 0.0f;

        // --- 4) fused butterfly: (sum, max_all, max_attack, min_attack) ---
        float mxatt = (lane < NK) ? xa : -INFINITY;
        float mnatt = (lane < NK) ? xa :  INFINITY;
        #pragma unroll
        for (int o = 16; o > 0; o >>= 1) {
            s     +=        __shfl_xor_sync(0xffffffffu, s,     o);
            mxa    = fmaxf(mxa,   __shfl_xor_sync(0xffffffffu, mxa,   o));
            mxatt  = fmaxf(mxatt, __shfl_xor_sync(0xffffffffu, mxatt, o));
            mnatt  = fminf(mnatt, __shfl_xor_sync(0xffffffffu, mnatt, o));
        }

        // --- 5) non-attack max; rare warp-uniform path reloads the (hot) row ---
        float mx_non;
        if (mxa == mxatt) {
            smask[warp][lane] = 0u;
            __syncwarp();
            if (lane < NK) atomicOr(&smask[warp][idx >> 5], 1u << (idx & 31));
            __syncwarp();
            float m = -INFINITY;
            const float4* rowp4 = reinterpret_cast<const float4*>(rowbase);
            #pragma unroll 2
            for (int j = 0; j < 8; j++) {
                int i = lane + 32 * j;
                if (i < NF4) {
                    float4 q = __ldg(rowp4 + i);
                    unsigned int bits = (smask[warp][i >> 3] >> ((i & 7) * 4)) & 0xFu;
                    if (!(bits & 1u)) m = fmaxf(m, q.x);
                    if (!(bits & 2u)) m = fmaxf(m, q.y);
                    if (!(bits & 4u)) m = fmaxf(m, q.z);
                    if (!(bits & 8u)) m = fmaxf(m, q.w);
                }
            }
            #pragma unroll
            for (int o = 16; o > 0; o >>= 1)
                m = fmaxf(m, __shfl_xor_sync(0xffffffffu, m, o));
            mx_non = m;
            __syncwarp();
        } else {
            mx_non = mxa;
        }

        // --- 6) probs + macro (pmin via monotonicity) ---
        float inv_s = __frcp_rn(s);
        float pmin     = ex2f(mnatt  * L2E) * inv_s;
        float pmax_non = ex2f(mx_non * L2E) * inv_s;
        float macro = pmax_non - pmin;

        // --- 7) sorting term ---
        float p = (lane < NK) ? (ex2f(xa * L2E) * inv_s) : 0.0f;
        float pnext = __shfl_down_sync(0xffffffffu, p, 1);
        float term = 0.0f;
        if (lane < NK - 1) {
            float d  = pnext - p;
            float sv = 5.0f + 5.0f * d;
            term = pow9f(sv);
        }
        #pragma unroll
        for (int o = 16; o > 0; o >>= 1)
            term += __shfl_xor_sync(0xffffffffu, term, o);

        if (lane == 0) {
            float gm9 = rootf(term * (1.0f / 9.0f), 1.0f / 9.0f);
            float sorting = (gm9 - 5.0f) * 0.2f;
            float c0 = 5.0f + 5.0f * macro;
            float c1 = 5.0f + 5.0f * sorting;
            float m = (pow10f(c0) + pow10f(c1)) * 0.5f;
            float fin = rootf(m, 0.1f);
            out[row] = (fin - 5.0f) * 0.2f;
        }
    }
}

extern "C" void kernel_launch(void* const* d_in, const int* in_sizes, int n_in,
                              void* d_out, int out_size)
{
    const float* y_pred   = (const float*)d_in[0];
    const int*   y_attack = (const int*)d_in[1];
    float*       out      = (float*)d_out;
    int nrows = in_sizes[1] / NK;   // 32768

    int blocks = NBLK;
    if (blocks * WPB > nrows) blocks = (nrows + WPB - 1) / WPB;
    boilerplate_loss_kernel<<<blocks, WPB * 32>>>(y_pred, y_attack, out, nrows);
}